// round 3
// baseline (speedup 1.0000x reference)
#include <cuda_runtime.h>

// Problem constants (fixed by setup_inputs): B=8, H=W=512, D=32, K=64
#define BATCH   8
#define NPIX    (512 * 512)
#define DIM     32
#define KINST   64
#define MARGIN  0.25f

// accum decomposition: one wave even at occupancy 4 (592 = 148 * 4)
#define BPB     74
#define THREADS 128
#define WARPS   (THREADS / 32)     // 4
#define CHUNK   ((NPIX + BPB - 1) / BPB)   // 3543

// hist decomposition
#define HBPB    32                 // hist blocks per batch
#define HCHUNK  (NPIX / HBPB)      // 8192

// Scratch (__device__ globals: allocs are banned)
__device__ float g_part_sums[BPB * BATCH * KINST * DIM];   // ~4.85 MB
__device__ float g_part_cnts[HBPB * BATCH * KINST];        // 64 KB
__device__ float g_sums[BATCH * KINST * DIM];
__device__ float g_counts[BATCH * KINST];

// ---------------------------------------------------------------------------
// Kernel 1: label histogram -> per-block partial counts (no atomics to gmem).
// grid = (HBPB, BATCH), 256 threads.
// ---------------------------------------------------------------------------
__global__ __launch_bounds__(256)
void hist_kernel(const int* __restrict__ lab) {
    __shared__ int h[KINST];
    const int b = blockIdx.y;
    for (int i = threadIdx.x; i < KINST; i += 256) h[i] = 0;
    __syncthreads();

    const int4* l4 = (const int4*)(lab + (size_t)b * NPIX + (size_t)blockIdx.x * HCHUNK);
    const int n4 = HCHUNK / 4;     // 2048 int4 per block
    for (int i = threadIdx.x; i < n4; i += 256) {
        int4 v = l4[i];
        atomicAdd(&h[v.x], 1);
        atomicAdd(&h[v.y], 1);
        atomicAdd(&h[v.z], 1);
        atomicAdd(&h[v.w], 1);
    }
    __syncthreads();
    for (int i = threadIdx.x; i < KINST; i += 256)
        g_part_cnts[(blockIdx.x * BATCH + b) * KINST + i] = (float)h[i];
}

// ---------------------------------------------------------------------------
// Kernel 2: segment accumulation into warp-private smem bins, then per-block
// partial sums to gmem (distinct slots, no atomics).
// grid = (BPB, BATCH), 128 threads (4 warps). smem = 32 KB -> occ >= 4.
// ---------------------------------------------------------------------------
__global__ __launch_bounds__(THREADS)
void accum_kernel(const float* __restrict__ emb, const int* __restrict__ lab) {
    __shared__ float bins[WARPS][KINST * DIM];   // 4 * 8KB = 32KB

    const int w    = threadIdx.x >> 5;
    const int lane = threadIdx.x & 31;
    const int b    = blockIdx.y;

    for (int i = threadIdx.x; i < WARPS * KINST * DIM; i += THREADS)
        (&bins[0][0])[i] = 0.0f;
    __syncthreads();

    const int p0 = blockIdx.x * CHUNK;
    const int p1 = (p0 + CHUNK < NPIX) ? (p0 + CHUNK) : NPIX;

    const float* __restrict__ e = emb + (size_t)b * NPIX * DIM;
    const int*   __restrict__ l = lab + (size_t)b * NPIX;

    float* mybins = &bins[w][lane];      // +k*DIM keeps bank == lane

    constexpr int U = 8;
    int p = p0 + w;
    for (; p + (U - 1) * WARPS < p1; p += U * WARPS) {
        float v[U];
        int   kk[U];
#pragma unroll
        for (int u = 0; u < U; u++) {
            const int pp = p + u * WARPS;
            v[u]  = __ldcs(&e[(size_t)pp * DIM + lane]);
            kk[u] = l[pp];
        }
#pragma unroll
        for (int u = 0; u < U; u++)
            mybins[kk[u] * DIM] += v[u];
    }
    for (; p < p1; p += WARPS) {
        float v = __ldcs(&e[(size_t)p * DIM + lane]);
        mybins[l[p] * DIM] += v;
    }
    __syncthreads();

    // fold 4 warp copies, write partial (coalesced STG)
    float* dst = &g_part_sums[((size_t)blockIdx.x * BATCH + b) * KINST * DIM];
    for (int i = threadIdx.x; i < KINST * DIM; i += THREADS) {
        float s = bins[0][i] + bins[1][i] + bins[2][i] + bins[3][i];
        dst[i] = s;
    }
}

// ---------------------------------------------------------------------------
// Kernel 3: wide reduction of partials. grid = 64 blocks * 256 = 16384 threads.
// Thread i owns one (b,k,d) slot; sums 74 partials (coalesced per j).
// Also reduces counts and zeroes out[0].
// ---------------------------------------------------------------------------
__global__ __launch_bounds__(256)
void reduce_kernel(float* __restrict__ out) {
    const int i = blockIdx.x * 256 + threadIdx.x;   // 0 .. 16383
    if (i == 0) out[0] = 0.0f;

    float s = 0.0f;
#pragma unroll 2
    for (int j = 0; j < BPB; j++)
        s += g_part_sums[(size_t)j * (BATCH * KINST * DIM) + i];
    g_sums[i] = s;

    if (i < BATCH * KINST) {
        float c = 0.0f;
#pragma unroll
        for (int j = 0; j < HBPB; j++)
            c += g_part_cnts[j * (BATCH * KINST) + i];
        g_counts[i] = c;
    }
}

// ---------------------------------------------------------------------------
// Kernel 4: finalize. One block per batch element.
// ---------------------------------------------------------------------------
#define CSTRIDE 33

__global__ __launch_bounds__(256)
void finalize_kernel(float* __restrict__ out) {
    __shared__ float c[KINST * CSTRIDE];
    __shared__ float cnt[KINST];
    __shared__ float acc_s;

    const int b   = blockIdx.x;
    const int tid = threadIdx.x;

    if (tid == 0) acc_s = 0.0f;
    for (int i = tid; i < KINST; i += blockDim.x)
        cnt[i] = g_counts[b * KINST + i];
    for (int i = tid; i < KINST * DIM; i += blockDim.x) {
        const int k = i / DIM, d = i - k * DIM;
        const float ct = g_counts[b * KINST + k];
        c[k * CSTRIDE + d] = g_sums[b * KINST * DIM + i] / fmaxf(ct, 1.0f);
    }
    __syncthreads();

    float acc = 0.0f;
    for (int t = tid; t < KINST * KINST; t += blockDim.x) {
        const int i = t / KINST, j = t - i * KINST;
        if (j > i && cnt[i] > 0.5f && cnt[j] > 0.5f) {
            float dsum = 0.0f;
#pragma unroll
            for (int d = 0; d < DIM; d++)
                dsum += fabsf(c[i * CSTRIDE + d] - c[j * CSTRIDE + d]);
            const float h = fmaxf(0.0f, MARGIN - dsum);
            acc += h * h;
        }
    }
#pragma unroll
    for (int off = 16; off > 0; off >>= 1)
        acc += __shfl_xor_sync(0xFFFFFFFFu, acc, off);
    if ((tid & 31) == 0) atomicAdd(&acc_s, acc);
    __syncthreads();

    if (tid == 0) {
        float n = 0.0f;
#pragma unroll
        for (int k = 0; k < KINST; k++) n += (cnt[k] > 0.5f) ? 1.0f : 0.0f;
        const float ncomp = n * (n - 1.0f) * 0.5f;
        atomicAdd(out, (acc_s / ncomp) * (1.0f / (float)BATCH));
    }
}

// ---------------------------------------------------------------------------
extern "C" void kernel_launch(void* const* d_in, const int* in_sizes, int n_in,
                              void* d_out, int out_size) {
    const float* emb = (const float*)d_in[0];
    const int*   lab = (const int*)d_in[1];
    float*       out = (float*)d_out;
    (void)in_sizes; (void)n_in; (void)out_size;

    hist_kernel<<<dim3(HBPB, BATCH), 256>>>(lab);
    accum_kernel<<<dim3(BPB, BATCH), THREADS>>>(emb, lab);
    reduce_kernel<<<64, 256>>>(out);
    finalize_kernel<<<BATCH, 256>>>(out);
}

// round 5
// speedup vs baseline: 1.3650x; 1.3650x over previous
#include <cuda_runtime.h>

// Problem constants (fixed by setup_inputs): B=8, H=W=512, D=32, K=64
#define BATCH   8
#define NPIX    (512 * 512)
#define DIM     32
#define KINST   64
#define MARGIN  0.25f

#define BPB     74                 // accum blocks per batch; 74*8 = 592 = 148*4
#define THREADS 128
#define WARPS   (THREADS / 32)     // 4
#define CHUNK   ((NPIX + BPB - 1) / BPB)   // 3543

// Scratch (__device__ globals: allocs are banned)
__device__ float g_part_sums[BPB * BATCH * KINST * DIM];   // ~4.85 MB
__device__ float g_part_cnts[BPB * BATCH * KINST];         // 1.2 MB
__device__ float g_sums[BATCH * KINST * DIM];
__device__ float g_counts[BATCH * KINST];

// ---------------------------------------------------------------------------
// Fillers: position accum at launch index 3 so ncu profiles it.
// ---------------------------------------------------------------------------
__global__ void zero_out_kernel(float* __restrict__ out) {
    if (threadIdx.x == 0) out[0] = 0.0f;
}
__global__ void nop_kernel() {}

// ---------------------------------------------------------------------------
// accum: software-pipelined segment accumulation.
// Warp-private smem bins: lane d owns dim d -> race-free, bank-conflict-free.
// Prefetch batch n+1's 16 LDGs before batch n's serialized smem RMW chain so
// DRAM loads stay in flight during the chain.
// grid = (BPB, BATCH), 128 threads. smem = 33 KB -> 4-6 blocks/SM.
// ---------------------------------------------------------------------------
#define U 16

__global__ __launch_bounds__(THREADS, 6)
void accum_kernel(const float* __restrict__ emb, const int* __restrict__ lab) {
    __shared__ float bins[WARPS][KINST * DIM];   // 32 KB
    __shared__ float cnts[WARPS][KINST];         // 1 KB

    const int w    = threadIdx.x >> 5;
    const int lane = threadIdx.x & 31;
    const int b    = blockIdx.y;

    for (int i = threadIdx.x; i < WARPS * KINST * DIM; i += THREADS)
        (&bins[0][0])[i] = 0.0f;
    for (int i = threadIdx.x; i < WARPS * KINST; i += THREADS)
        (&cnts[0][0])[i] = 0.0f;
    __syncthreads();

    const int p0 = blockIdx.x * CHUNK;
    const int p1 = (p0 + CHUNK < NPIX) ? (p0 + CHUNK) : NPIX;

    const float* __restrict__ e = emb + (size_t)b * NPIX * DIM;
    const int*   __restrict__ l = lab + (size_t)b * NPIX;

    float* mybins = &bins[w][lane];      // +k*DIM keeps bank == lane
    float* mycnts = &cnts[w][0];

    const int step = U * WARPS;          // 64
    int p = p0 + w;

    float v[U];
    int   kk[U];

    if (p + (U - 1) * WARPS < p1) {
        // prologue: load first batch
#pragma unroll
        for (int u = 0; u < U; u++) {
            const int pp = p + u * WARPS;
            v[u]  = __ldcs(&e[(size_t)pp * DIM + lane]);
            kk[u] = l[pp];
        }
        p += step;

        for (; p + (U - 1) * WARPS < p1; p += step) {
            float v2[U];
            int   kk2[U];
            // prefetch next batch (independent of the RMW chain below)
#pragma unroll
            for (int u = 0; u < U; u++) {
                const int pp = p + u * WARPS;
                v2[u]  = __ldcs(&e[(size_t)pp * DIM + lane]);
                kk2[u] = l[pp];
            }
            // consume current batch (serialized smem RMW chain)
#pragma unroll
            for (int u = 0; u < U; u++) {
                mybins[kk[u] * DIM] += v[u];
                if (lane == 0) mycnts[kk[u]] += 1.0f;
            }
#pragma unroll
            for (int u = 0; u < U; u++) { v[u] = v2[u]; kk[u] = kk2[u]; }
        }
        // epilogue: consume last full batch
#pragma unroll
        for (int u = 0; u < U; u++) {
            mybins[kk[u] * DIM] += v[u];
            if (lane == 0) mycnts[kk[u]] += 1.0f;
        }
    }
    // tail
    for (; p < p1; p += WARPS) {
        float tv = __ldcs(&e[(size_t)p * DIM + lane]);
        int  tk = l[p];
        mybins[tk * DIM] += tv;
        if (lane == 0) mycnts[tk] += 1.0f;
    }
    __syncthreads();

    // fold warp copies, write per-block partials (plain coalesced STG)
    float* dst = &g_part_sums[((size_t)blockIdx.x * BATCH + b) * KINST * DIM];
    for (int i = threadIdx.x; i < KINST * DIM; i += THREADS)
        dst[i] = bins[0][i] + bins[1][i] + bins[2][i] + bins[3][i];
    float* dct = &g_part_cnts[((size_t)blockIdx.x * BATCH + b) * KINST];
    for (int i = threadIdx.x; i < KINST; i += THREADS)
        dct[i] = cnts[0][i] + cnts[1][i] + cnts[2][i] + cnts[3][i];
}

// ---------------------------------------------------------------------------
// reduce: fold 74 partials. 64 blocks * 256 threads = 16384 = B*K*D slots.
// ---------------------------------------------------------------------------
__global__ __launch_bounds__(256)
void reduce_kernel() {
    const int i = blockIdx.x * 256 + threadIdx.x;   // 0 .. 16383
    float s = 0.0f;
#pragma unroll 2
    for (int j = 0; j < BPB; j++)
        s += g_part_sums[(size_t)j * (BATCH * KINST * DIM) + i];
    g_sums[i] = s;

    if (i < BATCH * KINST) {
        float c = 0.0f;
#pragma unroll 2
        for (int j = 0; j < BPB; j++)
            c += g_part_cnts[j * (BATCH * KINST) + i];
        g_counts[i] = c;
    }
}

// ---------------------------------------------------------------------------
// finalize: grid = (8 pair-slices, BATCH). Each block covers 512 of the 4096
// (i,j) cells for its batch. Centroids cached in smem, stride-33 padded.
// ---------------------------------------------------------------------------
#define CSTRIDE 33
#define FSLICES 8

__global__ __launch_bounds__(128)
void finalize_kernel(float* __restrict__ out) {
    __shared__ float c[KINST * CSTRIDE];
    __shared__ float cnt[KINST];
    __shared__ float wsum[4];

    const int b   = blockIdx.y;
    const int tid = threadIdx.x;

    for (int i = tid; i < KINST; i += 128)
        cnt[i] = g_counts[b * KINST + i];
    for (int i = tid; i < KINST * DIM; i += 128) {
        const int k = i >> 5, d = i & 31;
        c[k * CSTRIDE + d] = g_sums[b * KINST * DIM + i] / fmaxf(g_counts[b * KINST + k], 1.0f);
    }
    __syncthreads();

    const int t0 = blockIdx.x * (KINST * KINST / FSLICES);   // 512 cells per slice
    float acc = 0.0f;
    for (int t = t0 + tid; t < t0 + KINST * KINST / FSLICES; t += 128) {
        const int i = t >> 6, j = t & 63;
        if (j > i && cnt[i] > 0.5f && cnt[j] > 0.5f) {
            float dsum = 0.0f;
#pragma unroll
            for (int d = 0; d < DIM; d++)
                dsum += fabsf(c[i * CSTRIDE + d] - c[j * CSTRIDE + d]);
            const float h = fmaxf(0.0f, MARGIN - dsum);
            acc += h * h;
        }
    }
#pragma unroll
    for (int off = 16; off > 0; off >>= 1)
        acc += __shfl_xor_sync(0xFFFFFFFFu, acc, off);
    if ((tid & 31) == 0) wsum[tid >> 5] = acc;
    __syncthreads();

    if (tid == 0) {
        float n = 0.0f;
#pragma unroll
        for (int k = 0; k < KINST; k++) n += (cnt[k] > 0.5f) ? 1.0f : 0.0f;
        const float ncomp = n * (n - 1.0f) * 0.5f;
        const float part = wsum[0] + wsum[1] + wsum[2] + wsum[3];
        atomicAdd(out, part / (ncomp * (float)BATCH));
    }
}

// ---------------------------------------------------------------------------
extern "C" void kernel_launch(void* const* d_in, const int* in_sizes, int n_in,
                              void* d_out, int out_size) {
    const float* emb = (const float*)d_in[0];
    const int*   lab = (const int*)d_in[1];
    float*       out = (float*)d_out;
    (void)in_sizes; (void)n_in; (void)out_size;

    zero_out_kernel<<<1, 32>>>(out);                 // launch 0
    nop_kernel<<<1, 32>>>();                         // launch 1
    nop_kernel<<<1, 32>>>();                         // launch 2
    accum_kernel<<<dim3(BPB, BATCH), THREADS>>>(emb, lab);   // launch 3 <- profiled
    reduce_kernel<<<64, 256>>>();                    // launch 4
    finalize_kernel<<<dim3(FSLICES, BATCH), 128>>>(out);     // launch 5
}

// round 6
// speedup vs baseline: 1.8382x; 1.3467x over previous
#include <cuda_runtime.h>

// Problem constants (fixed by setup_inputs): B=8, H=W=512, D=32, K=64
#define BATCH   8
#define NPIX    (512 * 512)
#define DIM     32
#define KINST   64
#define MARGIN  0.25f

#define BPB     74                 // accum blocks per batch; 74*8 = 592 = 148*4
#define THREADS 128
#define WARPS   (THREADS / 32)     // 4
#define CHUNK   ((NPIX + BPB - 1) / BPB)   // 3543

#define HBPB    32                 // hist blocks per batch
#define HCHUNK  (NPIX / HBPB)      // 8192

// Scratch (__device__ globals: allocs are banned)
__device__ float g_part_sums[BPB * BATCH * KINST * DIM];   // ~4.85 MB
__device__ float g_part_cnts[HBPB * BATCH * KINST];        // 64 KB
__device__ float g_sums[BATCH * KINST * DIM];
__device__ float g_counts[BATCH * KINST];

// ---------------------------------------------------------------------------
__global__ void zero_out_kernel(float* __restrict__ out) {
    if (threadIdx.x == 0) out[0] = 0.0f;
}
__global__ void nop_kernel() {}

// ---------------------------------------------------------------------------
// hist: per-block partial label counts (smem atomics, no gmem atomics).
// ---------------------------------------------------------------------------
__global__ __launch_bounds__(256)
void hist_kernel(const int* __restrict__ lab) {
    __shared__ int h[KINST];
    const int b = blockIdx.y;
    for (int i = threadIdx.x; i < KINST; i += 256) h[i] = 0;
    __syncthreads();

    const int4* l4 = (const int4*)(lab + (size_t)b * NPIX + (size_t)blockIdx.x * HCHUNK);
    for (int i = threadIdx.x; i < HCHUNK / 4; i += 256) {
        int4 v = l4[i];
        atomicAdd(&h[v.x], 1);
        atomicAdd(&h[v.y], 1);
        atomicAdd(&h[v.z], 1);
        atomicAdd(&h[v.w], 1);
    }
    __syncthreads();
    for (int i = threadIdx.x; i < KINST; i += 256)
        g_part_cnts[(blockIdx.x * BATCH + b) * KINST + i] = (float)h[i];
}

// ---------------------------------------------------------------------------
// accum: float4-per-thread (8 threads/pixel, 4 pixels per LDG.128), warp-
// private smem bins, double-buffered (2 x 4 groups = 2 x 16 pixels in flight
// at only ~45 live regs so ptxas keeps the pipeline).
// Bin layout rotated by 8*(k&3) floats so the 4 pixel-groups of a warp hit
// disjoint banks when their labels differ mod 4.
// Physical float index for (k,d): k*32 + ((d + 8*(k&3)) & 31).
// grid = (BPB, BATCH), 128 threads. smem = 32 KB.
// ---------------------------------------------------------------------------
#define G 4   // groups per buffer; 1 group = 4 pixels = 1 LDG.128 per thread

__global__ __launch_bounds__(THREADS, 6)
void accum_kernel(const float* __restrict__ emb, const int* __restrict__ lab) {
    __shared__ float bins[WARPS][KINST * DIM];   // 32 KB

    const int w    = threadIdx.x >> 5;
    const int lane = threadIdx.x & 31;
    const int sub  = lane & 7;    // thread-in-pixel: dims 4*sub .. 4*sub+3
    const int pix  = lane >> 3;   // pixel-in-group: 0..3
    const int b    = blockIdx.y;

    for (int i = threadIdx.x; i < WARPS * KINST * DIM; i += THREADS)
        (&bins[0][0])[i] = 0.0f;
    __syncthreads();

    const int p0 = blockIdx.x * CHUNK;
    const int p1 = (p0 + CHUNK < NPIX) ? (p0 + CHUNK) : NPIX;

    const float*  __restrict__ e  = emb + (size_t)b * NPIX * DIM;
    const float4* __restrict__ e4 = (const float4*)e;
    const int*    __restrict__ l  = lab + (size_t)b * NPIX;

    float* mybin = &bins[w][0];

    // per iteration the block consumes WARPS*G*4 = 64 pixels;
    // warp w, group g covers pixels base + w*16 + g*4 + pix
    const int STEP = WARPS * G * 4;   // 64

    float4 v[G], v2[G];
    int    kk[G], kk2[G];

    int base = p0;
    if (base + STEP <= p1) {
        // prologue
#pragma unroll
        for (int g = 0; g < G; g++) {
            const int pp = base + w * 16 + g * 4 + pix;
            v[g]  = __ldcs(&e4[(size_t)pp * 8 + sub]);
            kk[g] = l[pp];
        }
        base += STEP;

        for (; base + STEP <= p1; base += STEP) {
            // prefetch next buffer (independent of chain below)
#pragma unroll
            for (int g = 0; g < G; g++) {
                const int pp = base + w * 16 + g * 4 + pix;
                v2[g]  = __ldcs(&e4[(size_t)pp * 8 + sub]);
                kk2[g] = l[pp];
            }
            // consume current buffer: vector RMW, rotated layout
#pragma unroll
            for (int g = 0; g < G; g++) {
                const int k   = kk[g];
                const int off = ((sub << 2) + ((k & 3) << 3)) & 31;
                float4* bp = (float4*)&mybin[(k << 5) + off];
                float4 cur = *bp;
                cur.x += v[g].x; cur.y += v[g].y;
                cur.z += v[g].z; cur.w += v[g].w;
                *bp = cur;
            }
#pragma unroll
            for (int g = 0; g < G; g++) { v[g] = v2[g]; kk[g] = kk2[g]; }
        }
        // epilogue: consume last buffer
#pragma unroll
        for (int g = 0; g < G; g++) {
            const int k   = kk[g];
            const int off = ((sub << 2) + ((k & 3) << 3)) & 31;
            float4* bp = (float4*)&mybin[(k << 5) + off];
            float4 cur = *bp;
            cur.x += v[g].x; cur.y += v[g].y;
            cur.z += v[g].z; cur.w += v[g].w;
            *bp = cur;
        }
    }
    // scalar tail: warp-per-pixel, lane = dim, same rotated layout
    for (int p = base + w; p < p1; p += WARPS) {
        const float tv = e[(size_t)p * DIM + lane];
        const int   k  = l[p];
        const int  off = (lane + ((k & 3) << 3)) & 31;
        mybin[(k << 5) + off] += tv;
    }
    __syncthreads();

    // fold warp copies (un-rotating), write per-block partials
    float* dst = &g_part_sums[((size_t)blockIdx.x * BATCH + b) * KINST * DIM];
    for (int i = threadIdx.x; i < KINST * DIM; i += THREADS) {
        const int k = i >> 5, d = i & 31;
        const int phys = (k << 5) + ((d + ((k & 3) << 3)) & 31);
        dst[i] = bins[0][phys] + bins[1][phys] + bins[2][phys] + bins[3][phys];
    }
}

// ---------------------------------------------------------------------------
// reduce: fold accum partials (74) and hist partials (32).
// 64 blocks * 256 threads = 16384 = B*K*D slots.
// ---------------------------------------------------------------------------
__global__ __launch_bounds__(256)
void reduce_kernel() {
    const int i = blockIdx.x * 256 + threadIdx.x;
    float s = 0.0f;
#pragma unroll 2
    for (int j = 0; j < BPB; j++)
        s += g_part_sums[(size_t)j * (BATCH * KINST * DIM) + i];
    g_sums[i] = s;

    if (i < BATCH * KINST) {
        float c = 0.0f;
#pragma unroll
        for (int j = 0; j < HBPB; j++)
            c += g_part_cnts[j * (BATCH * KINST) + i];
        g_counts[i] = c;
    }
}

// ---------------------------------------------------------------------------
// finalize: grid = (8 pair-slices, BATCH), centroids in smem (stride 33).
// ---------------------------------------------------------------------------
#define CSTRIDE 33
#define FSLICES 8

__global__ __launch_bounds__(128)
void finalize_kernel(float* __restrict__ out) {
    __shared__ float c[KINST * CSTRIDE];
    __shared__ float cnt[KINST];
    __shared__ float wsum[4];

    const int b   = blockIdx.y;
    const int tid = threadIdx.x;

    for (int i = tid; i < KINST; i += 128)
        cnt[i] = g_counts[b * KINST + i];
    for (int i = tid; i < KINST * DIM; i += 128) {
        const int k = i >> 5, d = i & 31;
        c[k * CSTRIDE + d] = g_sums[b * KINST * DIM + i] / fmaxf(g_counts[b * KINST + k], 1.0f);
    }
    __syncthreads();

    const int t0 = blockIdx.x * (KINST * KINST / FSLICES);
    float acc = 0.0f;
    for (int t = t0 + tid; t < t0 + KINST * KINST / FSLICES; t += 128) {
        const int i = t >> 6, j = t & 63;
        if (j > i && cnt[i] > 0.5f && cnt[j] > 0.5f) {
            float dsum = 0.0f;
#pragma unroll
            for (int d = 0; d < DIM; d++)
                dsum += fabsf(c[i * CSTRIDE + d] - c[j * CSTRIDE + d]);
            const float h = fmaxf(0.0f, MARGIN - dsum);
            acc += h * h;
        }
    }
#pragma unroll
    for (int off = 16; off > 0; off >>= 1)
        acc += __shfl_xor_sync(0xFFFFFFFFu, acc, off);
    if ((tid & 31) == 0) wsum[tid >> 5] = acc;
    __syncthreads();

    if (tid == 0) {
        float n = 0.0f;
#pragma unroll
        for (int k = 0; k < KINST; k++) n += (cnt[k] > 0.5f) ? 1.0f : 0.0f;
        const float ncomp = n * (n - 1.0f) * 0.5f;
        const float part = wsum[0] + wsum[1] + wsum[2] + wsum[3];
        atomicAdd(out, part / (ncomp * (float)BATCH));
    }
}

// ---------------------------------------------------------------------------
extern "C" void kernel_launch(void* const* d_in, const int* in_sizes, int n_in,
                              void* d_out, int out_size) {
    const float* emb = (const float*)d_in[0];
    const int*   lab = (const int*)d_in[1];
    float*       out = (float*)d_out;
    (void)in_sizes; (void)n_in; (void)out_size;

    zero_out_kernel<<<1, 32>>>(out);                          // launch 0
    hist_kernel<<<dim3(HBPB, BATCH), 256>>>(lab);             // launch 1
    nop_kernel<<<1, 32>>>();                                  // launch 2
    accum_kernel<<<dim3(BPB, BATCH), THREADS>>>(emb, lab);    // launch 3 <- profiled
    reduce_kernel<<<64, 256>>>();                             // launch 4
    finalize_kernel<<<dim3(FSLICES, BATCH), 128>>>(out);      // launch 5
}

// round 7
// speedup vs baseline: 1.9477x; 1.0596x over previous
#include <cuda_runtime.h>

// Problem constants (fixed by setup_inputs): B=8, H=W=512, D=32, K=64
#define BATCH   8
#define NPIX    (512 * 512)
#define DIM     32
#define KINST   64
#define MARGIN  0.25f

#define NSM     148
#define MAXBPB  148                // supports up to occupancy 8
#define THREADS 128
#define WARPS   (THREADS / 32)     // 4

#define HBPB    32                 // hist blocks per batch
#define HCHUNK  (NPIX / HBPB)      // 8192

// Scratch (__device__ globals: allocs are banned)
__device__ float g_part_sums[MAXBPB * BATCH * KINST * DIM];  // 9.7 MB
__device__ float g_part_cnts[HBPB * BATCH * KINST];          // 64 KB
__device__ float g_sums[BATCH * KINST * DIM];
__device__ float g_counts[BATCH * KINST];

// ---------------------------------------------------------------------------
__global__ void zero_out_kernel(float* __restrict__ out) {
    if (threadIdx.x == 0) out[0] = 0.0f;
}
__global__ void nop_kernel() {}

// ---------------------------------------------------------------------------
// hist: per-block partial label counts (smem atomics, no gmem atomics).
// ---------------------------------------------------------------------------
__global__ __launch_bounds__(256)
void hist_kernel(const int* __restrict__ lab) {
    __shared__ int h[KINST];
    const int b = blockIdx.y;
    for (int i = threadIdx.x; i < KINST; i += 256) h[i] = 0;
    __syncthreads();

    const int4* l4 = (const int4*)(lab + (size_t)b * NPIX + (size_t)blockIdx.x * HCHUNK);
    for (int i = threadIdx.x; i < HCHUNK / 4; i += 256) {
        int4 v = l4[i];
        atomicAdd(&h[v.x], 1);
        atomicAdd(&h[v.y], 1);
        atomicAdd(&h[v.z], 1);
        atomicAdd(&h[v.w], 1);
    }
    __syncthreads();
    for (int i = threadIdx.x; i < KINST; i += 256)
        g_part_cnts[(blockIdx.x * BATCH + b) * KINST + i] = (float)h[i];
}

// ---------------------------------------------------------------------------
// accum: float4-per-thread (8 threads/pixel, 4 pixels per LDG.128), warp-
// private smem bins, double-buffered. Labels fetched once per warp-iter by
// lanes 0..15 and distributed via shfl (replaces 16 redundant LDGs).
// Bin layout rotated by 8*(k&3) floats; physical index for (k,d):
//   k*32 + ((d + 8*(k&3)) & 31).
// grid = (bpb, BATCH) with bpb chosen at launch = NSM*occupancy/BATCH.
// ---------------------------------------------------------------------------
#define G 4   // groups per buffer; 1 group = 4 pixels = 1 LDG.128 per thread

__global__ __launch_bounds__(THREADS, 6)
void accum_kernel(const float* __restrict__ emb, const int* __restrict__ lab,
                  int chunk) {
    __shared__ float bins[WARPS][KINST * DIM];   // 32 KB

    const int w    = threadIdx.x >> 5;
    const int lane = threadIdx.x & 31;
    const int sub  = lane & 7;    // thread-in-pixel: dims 4*sub .. 4*sub+3
    const int pix  = lane >> 3;   // pixel-in-group: 0..3
    const int b    = blockIdx.y;

    for (int i = threadIdx.x; i < WARPS * KINST * DIM; i += THREADS)
        (&bins[0][0])[i] = 0.0f;
    __syncthreads();

    const int p0 = blockIdx.x * chunk;
    int p1 = p0 + chunk; if (p1 > NPIX) p1 = NPIX;

    const float*  __restrict__ e  = emb + (size_t)b * NPIX * DIM;
    const float4* __restrict__ e4 = (const float4*)e;
    const int*    __restrict__ l  = lab + (size_t)b * NPIX;

    float* mybin = &bins[w][0];

    const int STEP = WARPS * G * 4;   // 64 pixels per block-iter (16 per warp)

    float4 v[G], v2[G];
    int labreg = 0, labreg2;

    int base = p0;
    if (base + STEP <= p1) {
        // prologue: load first buffer
        if (lane < 16) labreg = l[base + w * 16 + lane];
#pragma unroll
        for (int g = 0; g < G; g++)
            v[g] = __ldcs(&e4[(size_t)(base + w * 16 + g * 4 + pix) * 8 + sub]);
        base += STEP;

        for (; base + STEP <= p1; base += STEP) {
            // prefetch next buffer (independent of chain below)
            labreg2 = (lane < 16) ? l[base + w * 16 + lane] : 0;
#pragma unroll
            for (int g = 0; g < G; g++)
                v2[g] = __ldcs(&e4[(size_t)(base + w * 16 + g * 4 + pix) * 8 + sub]);
            // consume current buffer: vector RMW, rotated layout
#pragma unroll
            for (int g = 0; g < G; g++) {
                const int k   = __shfl_sync(0xFFFFFFFFu, labreg, g * 4 + pix);
                const int off = ((sub << 2) + ((k & 3) << 3)) & 31;
                float4* bp = (float4*)&mybin[(k << 5) + off];
                float4 cur = *bp;
                cur.x += v[g].x; cur.y += v[g].y;
                cur.z += v[g].z; cur.w += v[g].w;
                *bp = cur;
            }
#pragma unroll
            for (int g = 0; g < G; g++) v[g] = v2[g];
            labreg = labreg2;
        }
        // epilogue: consume last buffer
#pragma unroll
        for (int g = 0; g < G; g++) {
            const int k   = __shfl_sync(0xFFFFFFFFu, labreg, g * 4 + pix);
            const int off = ((sub << 2) + ((k & 3) << 3)) & 31;
            float4* bp = (float4*)&mybin[(k << 5) + off];
            float4 cur = *bp;
            cur.x += v[g].x; cur.y += v[g].y;
            cur.z += v[g].z; cur.w += v[g].w;
            *bp = cur;
        }
    }
    // scalar tail: warp-per-pixel, lane = dim, same rotated layout
    for (int p = base + w; p < p1; p += WARPS) {
        const float tv = e[(size_t)p * DIM + lane];
        const int   k  = l[p];
        const int  off = (lane + ((k & 3) << 3)) & 31;
        mybin[(k << 5) + off] += tv;
    }
    __syncthreads();

    // fold warp copies (un-rotating), write per-block partials
    float* dst = &g_part_sums[((size_t)blockIdx.x * BATCH + b) * KINST * DIM];
    for (int i = threadIdx.x; i < KINST * DIM; i += THREADS) {
        const int k = i >> 5, d = i & 31;
        const int phys = (k << 5) + ((d + ((k & 3) << 3)) & 31);
        dst[i] = bins[0][phys] + bins[1][phys] + bins[2][phys] + bins[3][phys];
    }
}

// ---------------------------------------------------------------------------
// reduce: fold accum partials (nparts) and hist partials (32).
// 64 blocks * 256 threads = 16384 = B*K*D slots.
// ---------------------------------------------------------------------------
__global__ __launch_bounds__(256)
void reduce_kernel(int nparts) {
    const int i = blockIdx.x * 256 + threadIdx.x;
    float s = 0.0f;
    for (int j = 0; j < nparts; j++)
        s += g_part_sums[(size_t)j * (BATCH * KINST * DIM) + i];
    g_sums[i] = s;

    if (i < BATCH * KINST) {
        float c = 0.0f;
#pragma unroll
        for (int j = 0; j < HBPB; j++)
            c += g_part_cnts[j * (BATCH * KINST) + i];
        g_counts[i] = c;
    }
}

// ---------------------------------------------------------------------------
// finalize: grid = (8 pair-slices, BATCH), centroids in smem (stride 33).
// ---------------------------------------------------------------------------
#define CSTRIDE 33
#define FSLICES 8

__global__ __launch_bounds__(128)
void finalize_kernel(float* __restrict__ out) {
    __shared__ float c[KINST * CSTRIDE];
    __shared__ float cnt[KINST];
    __shared__ float wsum[4];

    const int b   = blockIdx.y;
    const int tid = threadIdx.x;

    for (int i = tid; i < KINST; i += 128)
        cnt[i] = g_counts[b * KINST + i];
    for (int i = tid; i < KINST * DIM; i += 128) {
        const int k = i >> 5, d = i & 31;
        c[k * CSTRIDE + d] = g_sums[b * KINST * DIM + i] / fmaxf(g_counts[b * KINST + k], 1.0f);
    }
    __syncthreads();

    const int t0 = blockIdx.x * (KINST * KINST / FSLICES);
    float acc = 0.0f;
    for (int t = t0 + tid; t < t0 + KINST * KINST / FSLICES; t += 128) {
        const int i = t >> 6, j = t & 63;
        if (j > i && cnt[i] > 0.5f && cnt[j] > 0.5f) {
            float dsum = 0.0f;
#pragma unroll
            for (int d = 0; d < DIM; d++)
                dsum += fabsf(c[i * CSTRIDE + d] - c[j * CSTRIDE + d]);
            const float h = fmaxf(0.0f, MARGIN - dsum);
            acc += h * h;
        }
    }
#pragma unroll
    for (int off = 16; off > 0; off >>= 1)
        acc += __shfl_xor_sync(0xFFFFFFFFu, acc, off);
    if ((tid & 31) == 0) wsum[tid >> 5] = acc;
    __syncthreads();

    if (tid == 0) {
        float n = 0.0f;
#pragma unroll
        for (int k = 0; k < KINST; k++) n += (cnt[k] > 0.5f) ? 1.0f : 0.0f;
        const float ncomp = n * (n - 1.0f) * 0.5f;
        const float part = wsum[0] + wsum[1] + wsum[2] + wsum[3];
        atomicAdd(out, part / (ncomp * (float)BATCH));
    }
}

// ---------------------------------------------------------------------------
extern "C" void kernel_launch(void* const* d_in, const int* in_sizes, int n_in,
                              void* d_out, int out_size) {
    const float* emb = (const float*)d_in[0];
    const int*   lab = (const int*)d_in[1];
    float*       out = (float*)d_out;
    (void)in_sizes; (void)n_in; (void)out_size;

    // Size the accum grid to exactly fill the chip at max occupancy.
    // Host-side read-only query: graph-capture safe (no allocs, no sync).
    int occ = 0;
    cudaOccupancyMaxActiveBlocksPerMultiprocessor(&occ, accum_kernel, THREADS, 0);
    if (occ < 1) occ = 1;
    int bpb = (NSM * occ) / BATCH;          // blocks per batch
    if (bpb < 1)      bpb = 1;
    if (bpb > MAXBPB) bpb = MAXBPB;
    const int chunk = (NPIX + bpb - 1) / bpb;

    zero_out_kernel<<<1, 32>>>(out);                               // launch 0
    hist_kernel<<<dim3(HBPB, BATCH), 256>>>(lab);                  // launch 1
    nop_kernel<<<1, 32>>>();                                       // launch 2
    accum_kernel<<<dim3(bpb, BATCH), THREADS>>>(emb, lab, chunk);  // launch 3 <- profiled
    reduce_kernel<<<64, 256>>>(bpb);                               // launch 4
    finalize_kernel<<<dim3(FSLICES, BATCH), 128>>>(out);           // launch 5
}